// round 2
// baseline (speedup 1.0000x reference)
#include <cuda_runtime.h>

// ---------------------------------------------------------------------------
// QBWBottleneck fp32 implicit-GEMM, cp.async 3-stage pipelined (R2).
//
//  conv1 1x1 s1 256->128 +BN+fq+relu  -> g_buf1 [32,128,56,56]
//  conv2 3x3 s2 128->128 +BN+fq+relu  -> g_buf2 [32,128,28,28]
//  conv3 1x1 s1 128->512 +BN+fq       -> g_buf1 reused [32,512,28,28]
//  sc    1x1 s2 256->512 +BN+fq ; out = relu(t3 + sc) -> d_out
// ---------------------------------------------------------------------------

#define EPSBN 1e-5f

__device__ float g_buf1[12845056];   // 51.4 MB
__device__ float g_buf2[3211264];    // 12.8 MB

__device__ __forceinline__ float fq(float y, float s) {
    float q = rintf(y / s);
    q = fminf(fmaxf(q, -127.f), 127.f);
    return q * s;
}

__device__ __forceinline__ unsigned su32(const void* p) {
    return (unsigned)__cvta_generic_to_shared(p);
}
#define CPA4(dst, src)                                                         \
    asm volatile("cp.async.ca.shared.global [%0], [%1], 4;" ::                 \
                 "r"(dst), "l"(src))
#define CPA4Z(dst, src, sz)                                                    \
    asm volatile("cp.async.ca.shared.global [%0], [%1], 4, %2;" ::             \
                 "r"(dst), "l"(src), "r"(sz))
#define CPCOMMIT() asm volatile("cp.async.commit_group;")
#define CPWAIT1()  asm volatile("cp.async.wait_group 1;")
#define CPWAIT0()  asm volatile("cp.async.wait_group 0;")

// BM=BN=128, BK=16, 256 threads, 8x8/thread, 3-stage smem.
#define COMPUTE_STEP(b)                                                        \
    _Pragma("unroll")                                                          \
    for (int kk = 0; kk < 16; ++kk) {                                          \
        float a[8], bv[8];                                                     \
        _Pragma("unroll")                                                      \
        for (int i = 0; i < 8; ++i) a[i] = As[b][kk][ty * 8 + i];              \
        _Pragma("unroll")                                                      \
        for (int j = 0; j < 8; ++j) bv[j] = Bs[b][kk][tx * 8 + j];             \
        _Pragma("unroll")                                                      \
        for (int i = 0; i < 8; ++i)                                            \
            _Pragma("unroll")                                                  \
            for (int j = 0; j < 8; ++j)                                        \
                acc[i][j] = fmaf(a[i], bv[j], acc[i][j]);                      \
    }

// ---------------------------------------------------------------------------
// conv1: 1x1 s1, C[128][100352] = W1[128,256] * X
// ---------------------------------------------------------------------------
__global__ __launch_bounds__(256, 2)
void conv1_k(const float* __restrict__ x, const float* __restrict__ w,
             const float* __restrict__ gg, const float* __restrict__ bb,
             const float* __restrict__ mm, const float* __restrict__ vv,
             const float* __restrict__ ss)
{
    __shared__ float As[3][16][128];
    __shared__ float Bs[3][16][128];
    const int t  = threadIdx.x;
    const int tx = t & 15, ty = t >> 4;
    const int jcol = t & 127, krow = t >> 7;
    const int jg = blockIdx.x * 128 + jcol;
    const int n  = jg / 3136, p = jg - n * 3136;
    const float* xb = x + n * 802816 + p;
    const int ai = t >> 1;
    const int ak = (t & 1) * 8;

    float acc[8][8];
#pragma unroll
    for (int i = 0; i < 8; ++i)
#pragma unroll
        for (int j = 0; j < 8; ++j) acc[i][j] = 0.f;

    auto issue = [&](int s) {
        const int b = s % 3;
        const int k0 = s * 16;
        unsigned ad = su32(&As[b][ak][ai]);
        const float* ap = w + ai * 256 + k0 + ak;
#pragma unroll
        for (int r = 0; r < 8; ++r) CPA4(ad + r * 512u, ap + r);
        unsigned bd = su32(&Bs[b][krow * 8][jcol]);
        const float* bp = xb + (k0 + krow * 8) * 3136;
#pragma unroll
        for (int r = 0; r < 8; ++r) CPA4(bd + r * 512u, bp + r * 3136);
        CPCOMMIT();
    };

    issue(0); issue(1);
    for (int s = 0; s < 16; ++s) {
        if (s < 15) { CPWAIT1(); } else { CPWAIT0(); }
        __syncthreads();
        if (s + 2 < 16) issue(s + 2);
        COMPUTE_STEP(s % 3);
    }

    const float s = *ss;
    float inv_[8], bia_[8];
#pragma unroll
    for (int i = 0; i < 8; ++i) {
        int co = ty * 8 + i;
        float iv = gg[co] / sqrtf(vv[co] + EPSBN);
        inv_[i] = iv;
        bia_[i] = bb[co] - mm[co] * iv;
    }
#pragma unroll
    for (int j = 0; j < 8; ++j) {
        int jj = blockIdx.x * 128 + tx * 8 + j;
        int nn = jj / 3136, pp = jj - nn * 3136;
        float* op = g_buf1 + nn * 401408 + pp;
#pragma unroll
        for (int i = 0; i < 8; ++i) {
            int co = ty * 8 + i;
            float y = acc[i][j] * inv_[i] + bia_[i];
            op[co * 3136] = fmaxf(fq(y, s), 0.f);
        }
    }
}

// ---------------------------------------------------------------------------
// conv2: 3x3 s2 pad1, 128->128. 72 pipelined (tap, k0) steps.
// ---------------------------------------------------------------------------
__global__ __launch_bounds__(256, 2)
void conv2_k(const float* __restrict__ w,
             const float* __restrict__ gg, const float* __restrict__ bb,
             const float* __restrict__ mm, const float* __restrict__ vv,
             const float* __restrict__ ss)
{
    __shared__ float As[3][16][128];
    __shared__ float Bs[3][16][128];
    const int t  = threadIdx.x;
    const int tx = t & 15, ty = t >> 4;
    const int jcol = t & 127, krow = t >> 7;
    const int jg = blockIdx.x * 128 + jcol;
    const int n  = jg / 784, p = jg - n * 784;
    const int ho = p / 28, wo = p - ho * 28;
    const int h0 = 2 * ho - 1, w0 = 2 * wo - 1;
    const float* o1n = g_buf1 + n * 401408;
    const int ai = t >> 1;
    const int ak = (t & 1) * 8;

    float acc[8][8];
#pragma unroll
    for (int i = 0; i < 8; ++i)
#pragma unroll
        for (int j = 0; j < 8; ++j) acc[i][j] = 0.f;

    auto issue = [&](int s) {
        const int b = s % 3;
        const int tap = s >> 3;
        const int k0 = (s & 7) * 16;
        const int kh = tap / 3, kw = tap - kh * 3;
        unsigned ad = su32(&As[b][ak][ai]);
        const float* ap = w + (ai * 128 + k0 + ak) * 9 + tap;
#pragma unroll
        for (int r = 0; r < 8; ++r) CPA4(ad + r * 512u, ap + r * 9);
        const int h = h0 + kh, wd = w0 + kw;
        const bool valid = ((unsigned)h < 56u) && ((unsigned)wd < 56u);
        const int sz = valid ? 4 : 0;
        const float* bp = valid ? (o1n + (k0 + krow * 8) * 3136 + h * 56 + wd)
                                : o1n;
        unsigned bd = su32(&Bs[b][krow * 8][jcol]);
#pragma unroll
        for (int r = 0; r < 8; ++r) CPA4Z(bd + r * 512u, bp + r * 3136, sz);
        CPCOMMIT();
    };

    issue(0); issue(1);
    for (int s = 0; s < 72; ++s) {
        if (s < 71) { CPWAIT1(); } else { CPWAIT0(); }
        __syncthreads();
        if (s + 2 < 72) issue(s + 2);
        COMPUTE_STEP(s % 3);
    }

    const float s = *ss;
    float inv_[8], bia_[8];
#pragma unroll
    for (int i = 0; i < 8; ++i) {
        int co = ty * 8 + i;
        float iv = gg[co] / sqrtf(vv[co] + EPSBN);
        inv_[i] = iv;
        bia_[i] = bb[co] - mm[co] * iv;
    }
#pragma unroll
    for (int j = 0; j < 8; ++j) {
        int jj = blockIdx.x * 128 + tx * 8 + j;
        int nn = jj / 784, pp = jj - nn * 784;
        float* op = g_buf2 + nn * 100352 + pp;
#pragma unroll
        for (int i = 0; i < 8; ++i) {
            int co = ty * 8 + i;
            float y = acc[i][j] * inv_[i] + bia_[i];
            op[co * 784] = fmaxf(fq(y, s), 0.f);
        }
    }
}

// ---------------------------------------------------------------------------
// conv3: 1x1, 128->512, no relu, writes into g_buf1 ([n][512][784]).
// ---------------------------------------------------------------------------
__global__ __launch_bounds__(256, 2)
void conv3_k(const float* __restrict__ w,
             const float* __restrict__ gg, const float* __restrict__ bb,
             const float* __restrict__ mm, const float* __restrict__ vv,
             const float* __restrict__ ss)
{
    __shared__ float As[3][16][128];
    __shared__ float Bs[3][16][128];
    const int t  = threadIdx.x;
    const int tx = t & 15, ty = t >> 4;
    const int jcol = t & 127, krow = t >> 7;
    const int coT = blockIdx.y * 128;
    const int jg = blockIdx.x * 128 + jcol;
    const int n  = jg / 784, p = jg - n * 784;
    const float* o2b = g_buf2 + n * 100352 + p;
    const int ai = t >> 1;
    const int ak = (t & 1) * 8;

    float acc[8][8];
#pragma unroll
    for (int i = 0; i < 8; ++i)
#pragma unroll
        for (int j = 0; j < 8; ++j) acc[i][j] = 0.f;

    auto issue = [&](int s) {
        const int b = s % 3;
        const int k0 = s * 16;
        unsigned ad = su32(&As[b][ak][ai]);
        const float* ap = w + (coT + ai) * 128 + k0 + ak;
#pragma unroll
        for (int r = 0; r < 8; ++r) CPA4(ad + r * 512u, ap + r);
        unsigned bd = su32(&Bs[b][krow * 8][jcol]);
        const float* bp = o2b + (k0 + krow * 8) * 784;
#pragma unroll
        for (int r = 0; r < 8; ++r) CPA4(bd + r * 512u, bp + r * 784);
        CPCOMMIT();
    };

    issue(0); issue(1);
    for (int s = 0; s < 8; ++s) {
        if (s < 7) { CPWAIT1(); } else { CPWAIT0(); }
        __syncthreads();
        if (s + 2 < 8) issue(s + 2);
        COMPUTE_STEP(s % 3);
    }

    const float s = *ss;
    float inv_[8], bia_[8];
#pragma unroll
    for (int i = 0; i < 8; ++i) {
        int co = coT + ty * 8 + i;
        float iv = gg[co] / sqrtf(vv[co] + EPSBN);
        inv_[i] = iv;
        bia_[i] = bb[co] - mm[co] * iv;
    }
#pragma unroll
    for (int j = 0; j < 8; ++j) {
        int jj = blockIdx.x * 128 + tx * 8 + j;
        int nn = jj / 784, pp = jj - nn * 784;
        float* op = g_buf1 + nn * 401408 + (coT + ty * 8) * 784 + pp;
#pragma unroll
        for (int i = 0; i < 8; ++i) {
            float y = acc[i][j] * inv_[i] + bia_[i];
            op[i * 784] = fq(y, s);
        }
    }
}

// ---------------------------------------------------------------------------
// conv4: shortcut 1x1 s2, 256->512, fq; out = relu(t3 + sc).
// ---------------------------------------------------------------------------
__global__ __launch_bounds__(256, 2)
void conv4_k(const float* __restrict__ x, const float* __restrict__ w,
             const float* __restrict__ gg, const float* __restrict__ bb,
             const float* __restrict__ mm, const float* __restrict__ vv,
             const float* __restrict__ ss, float* __restrict__ out)
{
    __shared__ float As[3][16][128];
    __shared__ float Bs[3][16][128];
    const int t  = threadIdx.x;
    const int tx = t & 15, ty = t >> 4;
    const int jcol = t & 127, krow = t >> 7;
    const int coT = blockIdx.y * 128;
    const int jg = blockIdx.x * 128 + jcol;
    const int n  = jg / 784, p = jg - n * 784;
    const int ho = p / 28, wo = p - ho * 28;
    const float* xb = x + n * 802816 + (2 * ho) * 56 + 2 * wo;
    const int ai = t >> 1;
    const int ak = (t & 1) * 8;

    float acc[8][8];
#pragma unroll
    for (int i = 0; i < 8; ++i)
#pragma unroll
        for (int j = 0; j < 8; ++j) acc[i][j] = 0.f;

    auto issue = [&](int s) {
        const int b = s % 3;
        const int k0 = s * 16;
        unsigned ad = su32(&As[b][ak][ai]);
        const float* ap = w + (coT + ai) * 256 + k0 + ak;
#pragma unroll
        for (int r = 0; r < 8; ++r) CPA4(ad + r * 512u, ap + r);
        unsigned bd = su32(&Bs[b][krow * 8][jcol]);
        const float* bp = xb + (k0 + krow * 8) * 3136;
#pragma unroll
        for (int r = 0; r < 8; ++r) CPA4(bd + r * 512u, bp + r * 3136);
        CPCOMMIT();
    };

    issue(0); issue(1);
    for (int s = 0; s < 16; ++s) {
        if (s < 15) { CPWAIT1(); } else { CPWAIT0(); }
        __syncthreads();
        if (s + 2 < 16) issue(s + 2);
        COMPUTE_STEP(s % 3);
    }

    const float s = *ss;
    float inv_[8], bia_[8];
#pragma unroll
    for (int i = 0; i < 8; ++i) {
        int co = coT + ty * 8 + i;
        float iv = gg[co] / sqrtf(vv[co] + EPSBN);
        inv_[i] = iv;
        bia_[i] = bb[co] - mm[co] * iv;
    }
#pragma unroll
    for (int j = 0; j < 8; ++j) {
        int jj = blockIdx.x * 128 + tx * 8 + j;
        int nn = jj / 784, pp = jj - nn * 784;
        int base = nn * 401408 + (coT + ty * 8) * 784 + pp;
        const float* t3 = g_buf1 + base;
        float* op = out + base;
#pragma unroll
        for (int i = 0; i < 8; ++i) {
            float y  = acc[i][j] * inv_[i] + bia_[i];
            float qs = fq(y, s);
            op[i * 784] = fmaxf(t3[i * 784] + qs, 0.f);
        }
    }
}

// ---------------------------------------------------------------------------
extern "C" void kernel_launch(void* const* d_in, const int* in_sizes, int n_in,
                              void* d_out, int out_size)
{
    const float* x  = (const float*)d_in[0];
    const float* w1 = (const float*)d_in[1];
    const float* g1 = (const float*)d_in[2];
    const float* b1 = (const float*)d_in[3];
    const float* m1 = (const float*)d_in[4];
    const float* v1 = (const float*)d_in[5];
    const float* s1 = (const float*)d_in[6];
    const float* w2 = (const float*)d_in[7];
    const float* g2 = (const float*)d_in[8];
    const float* b2 = (const float*)d_in[9];
    const float* m2 = (const float*)d_in[10];
    const float* v2 = (const float*)d_in[11];
    const float* s2 = (const float*)d_in[12];
    const float* w3 = (const float*)d_in[13];
    const float* g3 = (const float*)d_in[14];
    const float* b3 = (const float*)d_in[15];
    const float* m3 = (const float*)d_in[16];
    const float* v3 = (const float*)d_in[17];
    const float* s3 = (const float*)d_in[18];
    const float* ws = (const float*)d_in[19];
    const float* gs = (const float*)d_in[20];
    const float* bs = (const float*)d_in[21];
    const float* ms = (const float*)d_in[22];
    const float* vs = (const float*)d_in[23];
    const float* ss = (const float*)d_in[24];

    conv1_k<<<784, 256>>>(x, w1, g1, b1, m1, v1, s1);
    conv2_k<<<196, 256>>>(w2, g2, b2, m2, v2, s2);
    conv3_k<<<dim3(196, 4), 256>>>(w3, g3, b3, m3, v3, s3);
    conv4_k<<<dim3(196, 4), 256>>>(x, ws, gs, bs, ms, vs, ss, (float*)d_out);
}

// round 3
// speedup vs baseline: 1.0019x; 1.0019x over previous
#include <cuda_runtime.h>

// ---------------------------------------------------------------------------
// QBWBottleneck fp32 implicit-GEMM, cp.async 3-stage pipelined (R2).
//
//  conv1 1x1 s1 256->128 +BN+fq+relu  -> g_buf1 [32,128,56,56]
//  conv2 3x3 s2 128->128 +BN+fq+relu  -> g_buf2 [32,128,28,28]
//  conv3 1x1 s1 128->512 +BN+fq       -> g_buf1 reused [32,512,28,28]
//  sc    1x1 s2 256->512 +BN+fq ; out = relu(t3 + sc) -> d_out
// ---------------------------------------------------------------------------

#define EPSBN 1e-5f

__device__ float g_buf1[12845056];   // 51.4 MB
__device__ float g_buf2[3211264];    // 12.8 MB

__device__ __forceinline__ float fq(float y, float s) {
    float q = rintf(y / s);
    q = fminf(fmaxf(q, -127.f), 127.f);
    return q * s;
}

__device__ __forceinline__ unsigned su32(const void* p) {
    return (unsigned)__cvta_generic_to_shared(p);
}
#define CPA4(dst, src)                                                         \
    asm volatile("cp.async.ca.shared.global [%0], [%1], 4;" ::                 \
                 "r"(dst), "l"(src))
#define CPA4Z(dst, src, sz)                                                    \
    asm volatile("cp.async.ca.shared.global [%0], [%1], 4, %2;" ::             \
                 "r"(dst), "l"(src), "r"(sz))
#define CPCOMMIT() asm volatile("cp.async.commit_group;")
#define CPWAIT1()  asm volatile("cp.async.wait_group 1;")
#define CPWAIT0()  asm volatile("cp.async.wait_group 0;")

// BM=BN=128, BK=16, 256 threads, 8x8/thread, 3-stage smem.
#define COMPUTE_STEP(b)                                                        \
    _Pragma("unroll")                                                          \
    for (int kk = 0; kk < 16; ++kk) {                                          \
        float a[8], bv[8];                                                     \
        _Pragma("unroll")                                                      \
        for (int i = 0; i < 8; ++i) a[i] = As[b][kk][ty * 8 + i];              \
        _Pragma("unroll")                                                      \
        for (int j = 0; j < 8; ++j) bv[j] = Bs[b][kk][tx * 8 + j];             \
        _Pragma("unroll")                                                      \
        for (int i = 0; i < 8; ++i)                                            \
            _Pragma("unroll")                                                  \
            for (int j = 0; j < 8; ++j)                                        \
                acc[i][j] = fmaf(a[i], bv[j], acc[i][j]);                      \
    }

// ---------------------------------------------------------------------------
// conv1: 1x1 s1, C[128][100352] = W1[128,256] * X
// ---------------------------------------------------------------------------
__global__ __launch_bounds__(256, 2)
void conv1_k(const float* __restrict__ x, const float* __restrict__ w,
             const float* __restrict__ gg, const float* __restrict__ bb,
             const float* __restrict__ mm, const float* __restrict__ vv,
             const float* __restrict__ ss)
{
    __shared__ float As[3][16][128];
    __shared__ float Bs[3][16][128];
    const int t  = threadIdx.x;
    const int tx = t & 15, ty = t >> 4;
    const int jcol = t & 127, krow = t >> 7;
    const int jg = blockIdx.x * 128 + jcol;
    const int n  = jg / 3136, p = jg - n * 3136;
    const float* xb = x + n * 802816 + p;
    const int ai = t >> 1;
    const int ak = (t & 1) * 8;

    float acc[8][8];
#pragma unroll
    for (int i = 0; i < 8; ++i)
#pragma unroll
        for (int j = 0; j < 8; ++j) acc[i][j] = 0.f;

    auto issue = [&](int s) {
        const int b = s % 3;
        const int k0 = s * 16;
        unsigned ad = su32(&As[b][ak][ai]);
        const float* ap = w + ai * 256 + k0 + ak;
#pragma unroll
        for (int r = 0; r < 8; ++r) CPA4(ad + r * 512u, ap + r);
        unsigned bd = su32(&Bs[b][krow * 8][jcol]);
        const float* bp = xb + (k0 + krow * 8) * 3136;
#pragma unroll
        for (int r = 0; r < 8; ++r) CPA4(bd + r * 512u, bp + r * 3136);
        CPCOMMIT();
    };

    issue(0); issue(1);
    for (int s = 0; s < 16; ++s) {
        if (s < 15) { CPWAIT1(); } else { CPWAIT0(); }
        __syncthreads();
        if (s + 2 < 16) issue(s + 2);
        COMPUTE_STEP(s % 3);
    }

    const float s = *ss;
    float inv_[8], bia_[8];
#pragma unroll
    for (int i = 0; i < 8; ++i) {
        int co = ty * 8 + i;
        float iv = gg[co] / sqrtf(vv[co] + EPSBN);
        inv_[i] = iv;
        bia_[i] = bb[co] - mm[co] * iv;
    }
#pragma unroll
    for (int j = 0; j < 8; ++j) {
        int jj = blockIdx.x * 128 + tx * 8 + j;
        int nn = jj / 3136, pp = jj - nn * 3136;
        float* op = g_buf1 + nn * 401408 + pp;
#pragma unroll
        for (int i = 0; i < 8; ++i) {
            int co = ty * 8 + i;
            float y = acc[i][j] * inv_[i] + bia_[i];
            op[co * 3136] = fmaxf(fq(y, s), 0.f);
        }
    }
}

// ---------------------------------------------------------------------------
// conv2: 3x3 s2 pad1, 128->128. 72 pipelined (tap, k0) steps.
// ---------------------------------------------------------------------------
__global__ __launch_bounds__(256, 2)
void conv2_k(const float* __restrict__ w,
             const float* __restrict__ gg, const float* __restrict__ bb,
             const float* __restrict__ mm, const float* __restrict__ vv,
             const float* __restrict__ ss)
{
    __shared__ float As[3][16][128];
    __shared__ float Bs[3][16][128];
    const int t  = threadIdx.x;
    const int tx = t & 15, ty = t >> 4;
    const int jcol = t & 127, krow = t >> 7;
    const int jg = blockIdx.x * 128 + jcol;
    const int n  = jg / 784, p = jg - n * 784;
    const int ho = p / 28, wo = p - ho * 28;
    const int h0 = 2 * ho - 1, w0 = 2 * wo - 1;
    const float* o1n = g_buf1 + n * 401408;
    const int ai = t >> 1;
    const int ak = (t & 1) * 8;

    float acc[8][8];
#pragma unroll
    for (int i = 0; i < 8; ++i)
#pragma unroll
        for (int j = 0; j < 8; ++j) acc[i][j] = 0.f;

    auto issue = [&](int s) {
        const int b = s % 3;
        const int tap = s >> 3;
        const int k0 = (s & 7) * 16;
        const int kh = tap / 3, kw = tap - kh * 3;
        unsigned ad = su32(&As[b][ak][ai]);
        const float* ap = w + (ai * 128 + k0 + ak) * 9 + tap;
#pragma unroll
        for (int r = 0; r < 8; ++r) CPA4(ad + r * 512u, ap + r * 9);
        const int h = h0 + kh, wd = w0 + kw;
        const bool valid = ((unsigned)h < 56u) && ((unsigned)wd < 56u);
        const int sz = valid ? 4 : 0;
        const float* bp = valid ? (o1n + (k0 + krow * 8) * 3136 + h * 56 + wd)
                                : o1n;
        unsigned bd = su32(&Bs[b][krow * 8][jcol]);
#pragma unroll
        for (int r = 0; r < 8; ++r) CPA4Z(bd + r * 512u, bp + r * 3136, sz);
        CPCOMMIT();
    };

    issue(0); issue(1);
    for (int s = 0; s < 72; ++s) {
        if (s < 71) { CPWAIT1(); } else { CPWAIT0(); }
        __syncthreads();
        if (s + 2 < 72) issue(s + 2);
        COMPUTE_STEP(s % 3);
    }

    const float s = *ss;
    float inv_[8], bia_[8];
#pragma unroll
    for (int i = 0; i < 8; ++i) {
        int co = ty * 8 + i;
        float iv = gg[co] / sqrtf(vv[co] + EPSBN);
        inv_[i] = iv;
        bia_[i] = bb[co] - mm[co] * iv;
    }
#pragma unroll
    for (int j = 0; j < 8; ++j) {
        int jj = blockIdx.x * 128 + tx * 8 + j;
        int nn = jj / 784, pp = jj - nn * 784;
        float* op = g_buf2 + nn * 100352 + pp;
#pragma unroll
        for (int i = 0; i < 8; ++i) {
            int co = ty * 8 + i;
            float y = acc[i][j] * inv_[i] + bia_[i];
            op[co * 784] = fmaxf(fq(y, s), 0.f);
        }
    }
}

// ---------------------------------------------------------------------------
// conv3: 1x1, 128->512, no relu, writes into g_buf1 ([n][512][784]).
// ---------------------------------------------------------------------------
__global__ __launch_bounds__(256, 2)
void conv3_k(const float* __restrict__ w,
             const float* __restrict__ gg, const float* __restrict__ bb,
             const float* __restrict__ mm, const float* __restrict__ vv,
             const float* __restrict__ ss)
{
    __shared__ float As[3][16][128];
    __shared__ float Bs[3][16][128];
    const int t  = threadIdx.x;
    const int tx = t & 15, ty = t >> 4;
    const int jcol = t & 127, krow = t >> 7;
    const int coT = blockIdx.y * 128;
    const int jg = blockIdx.x * 128 + jcol;
    const int n  = jg / 784, p = jg - n * 784;
    const float* o2b = g_buf2 + n * 100352 + p;
    const int ai = t >> 1;
    const int ak = (t & 1) * 8;

    float acc[8][8];
#pragma unroll
    for (int i = 0; i < 8; ++i)
#pragma unroll
        for (int j = 0; j < 8; ++j) acc[i][j] = 0.f;

    auto issue = [&](int s) {
        const int b = s % 3;
        const int k0 = s * 16;
        unsigned ad = su32(&As[b][ak][ai]);
        const float* ap = w + (coT + ai) * 128 + k0 + ak;
#pragma unroll
        for (int r = 0; r < 8; ++r) CPA4(ad + r * 512u, ap + r);
        unsigned bd = su32(&Bs[b][krow * 8][jcol]);
        const float* bp = o2b + (k0 + krow * 8) * 784;
#pragma unroll
        for (int r = 0; r < 8; ++r) CPA4(bd + r * 512u, bp + r * 784);
        CPCOMMIT();
    };

    issue(0); issue(1);
    for (int s = 0; s < 8; ++s) {
        if (s < 7) { CPWAIT1(); } else { CPWAIT0(); }
        __syncthreads();
        if (s + 2 < 8) issue(s + 2);
        COMPUTE_STEP(s % 3);
    }

    const float s = *ss;
    float inv_[8], bia_[8];
#pragma unroll
    for (int i = 0; i < 8; ++i) {
        int co = coT + ty * 8 + i;
        float iv = gg[co] / sqrtf(vv[co] + EPSBN);
        inv_[i] = iv;
        bia_[i] = bb[co] - mm[co] * iv;
    }
#pragma unroll
    for (int j = 0; j < 8; ++j) {
        int jj = blockIdx.x * 128 + tx * 8 + j;
        int nn = jj / 784, pp = jj - nn * 784;
        float* op = g_buf1 + nn * 401408 + (coT + ty * 8) * 784 + pp;
#pragma unroll
        for (int i = 0; i < 8; ++i) {
            float y = acc[i][j] * inv_[i] + bia_[i];
            op[i * 784] = fq(y, s);
        }
    }
}

// ---------------------------------------------------------------------------
// conv4: shortcut 1x1 s2, 256->512, fq; out = relu(t3 + sc).
// ---------------------------------------------------------------------------
__global__ __launch_bounds__(256, 2)
void conv4_k(const float* __restrict__ x, const float* __restrict__ w,
             const float* __restrict__ gg, const float* __restrict__ bb,
             const float* __restrict__ mm, const float* __restrict__ vv,
             const float* __restrict__ ss, float* __restrict__ out)
{
    __shared__ float As[3][16][128];
    __shared__ float Bs[3][16][128];
    const int t  = threadIdx.x;
    const int tx = t & 15, ty = t >> 4;
    const int jcol = t & 127, krow = t >> 7;
    const int coT = blockIdx.y * 128;
    const int jg = blockIdx.x * 128 + jcol;
    const int n  = jg / 784, p = jg - n * 784;
    const int ho = p / 28, wo = p - ho * 28;
    const float* xb = x + n * 802816 + (2 * ho) * 56 + 2 * wo;
    const int ai = t >> 1;
    const int ak = (t & 1) * 8;

    float acc[8][8];
#pragma unroll
    for (int i = 0; i < 8; ++i)
#pragma unroll
        for (int j = 0; j < 8; ++j) acc[i][j] = 0.f;

    auto issue = [&](int s) {
        const int b = s % 3;
        const int k0 = s * 16;
        unsigned ad = su32(&As[b][ak][ai]);
        const float* ap = w + (coT + ai) * 256 + k0 + ak;
#pragma unroll
        for (int r = 0; r < 8; ++r) CPA4(ad + r * 512u, ap + r);
        unsigned bd = su32(&Bs[b][krow * 8][jcol]);
        const float* bp = xb + (k0 + krow * 8) * 3136;
#pragma unroll
        for (int r = 0; r < 8; ++r) CPA4(bd + r * 512u, bp + r * 3136);
        CPCOMMIT();
    };

    issue(0); issue(1);
    for (int s = 0; s < 16; ++s) {
        if (s < 15) { CPWAIT1(); } else { CPWAIT0(); }
        __syncthreads();
        if (s + 2 < 16) issue(s + 2);
        COMPUTE_STEP(s % 3);
    }

    const float s = *ss;
    float inv_[8], bia_[8];
#pragma unroll
    for (int i = 0; i < 8; ++i) {
        int co = coT + ty * 8 + i;
        float iv = gg[co] / sqrtf(vv[co] + EPSBN);
        inv_[i] = iv;
        bia_[i] = bb[co] - mm[co] * iv;
    }
#pragma unroll
    for (int j = 0; j < 8; ++j) {
        int jj = blockIdx.x * 128 + tx * 8 + j;
        int nn = jj / 784, pp = jj - nn * 784;
        int base = nn * 401408 + (coT + ty * 8) * 784 + pp;
        const float* t3 = g_buf1 + base;
        float* op = out + base;
#pragma unroll
        for (int i = 0; i < 8; ++i) {
            float y  = acc[i][j] * inv_[i] + bia_[i];
            float qs = fq(y, s);
            op[i * 784] = fmaxf(t3[i * 784] + qs, 0.f);
        }
    }
}

// ---------------------------------------------------------------------------
extern "C" void kernel_launch(void* const* d_in, const int* in_sizes, int n_in,
                              void* d_out, int out_size)
{
    const float* x  = (const float*)d_in[0];
    const float* w1 = (const float*)d_in[1];
    const float* g1 = (const float*)d_in[2];
    const float* b1 = (const float*)d_in[3];
    const float* m1 = (const float*)d_in[4];
    const float* v1 = (const float*)d_in[5];
    const float* s1 = (const float*)d_in[6];
    const float* w2 = (const float*)d_in[7];
    const float* g2 = (const float*)d_in[8];
    const float* b2 = (const float*)d_in[9];
    const float* m2 = (const float*)d_in[10];
    const float* v2 = (const float*)d_in[11];
    const float* s2 = (const float*)d_in[12];
    const float* w3 = (const float*)d_in[13];
    const float* g3 = (const float*)d_in[14];
    const float* b3 = (const float*)d_in[15];
    const float* m3 = (const float*)d_in[16];
    const float* v3 = (const float*)d_in[17];
    const float* s3 = (const float*)d_in[18];
    const float* ws = (const float*)d_in[19];
    const float* gs = (const float*)d_in[20];
    const float* bs = (const float*)d_in[21];
    const float* ms = (const float*)d_in[22];
    const float* vs = (const float*)d_in[23];
    const float* ss = (const float*)d_in[24];

    conv1_k<<<784, 256>>>(x, w1, g1, b1, m1, v1, s1);
    conv2_k<<<196, 256>>>(w2, g2, b2, m2, v2, s2);
    conv3_k<<<dim3(196, 4), 256>>>(w3, g3, b3, m3, v3, s3);
    conv4_k<<<dim3(196, 4), 256>>>(x, ws, gs, bs, ms, vs, ss, (float*)d_out);
}

// round 11
// speedup vs baseline: 1.0632x; 1.0612x over previous
#include <cuda_runtime.h>
#include <cstdint>

// ---------------------------------------------------------------------------
// QBWBottleneck fp32 implicit-GEMM with Blackwell packed f32x2 FMA (R11).
// Numerics are BIT-IDENTICAL to the R1 baseline (each packed lane is an
// independent IEEE fp32 FMA, same accumulation order per element).
//
//  conv1 1x1 s1 256->128 +BN+fq+relu  -> g_buf1 [32,128,56,56]
//  conv2 3x3 s2 128->128 +BN+fq+relu  -> g_buf2 [32,128,28,28]
//  conv3 1x1 s1 128->512 +BN+fq       -> g_buf1 reused [32,512,28,28]
//  sc    1x1 s2 256->512 +BN+fq ; out = relu(t3 + sc) -> d_out
// ---------------------------------------------------------------------------

#define EPSBN 1e-5f
typedef unsigned long long u64;

__device__ float g_buf1[12845056];   // 51.4 MB
__device__ float g_buf2[3211264];    // 12.8 MB

__device__ __forceinline__ float fq(float y, float s) {
    float q = rintf(y / s);
    q = fminf(fmaxf(q, -127.f), 127.f);
    return q * s;
}

// ---- packed fp32x2 helpers -------------------------------------------------
__device__ __forceinline__ u64 packdup(float a) {
    u64 r;
    asm("mov.b64 %0, {%1, %1};" : "=l"(r) : "r"(__float_as_uint(a)));
    return r;
}
__device__ __forceinline__ void fma2(u64& d, u64 a, u64 b) {
    asm("fma.rn.f32x2 %0, %1, %2, %0;" : "+l"(d) : "l"(a), "l"(b));
}
__device__ __forceinline__ float2 unpk(u64 v) {
    uint32_t lo, hi;
    asm("mov.b64 {%0, %1}, %2;" : "=r"(lo), "=r"(hi) : "l"(v));
    return make_float2(__uint_as_float(lo), __uint_as_float(hi));
}

// BM=BN=128, BK=16, 256 threads, 8x8 per thread (acc packed as 8x4 f32x2).
#define GEMM_COMPUTE_STEP()                                                    \
    __syncthreads();                                                           \
    _Pragma("unroll")                                                          \
    for (int kk = 0; kk < 16; ++kk) {                                          \
        u64 a2[8], b2[4];                                                      \
        _Pragma("unroll")                                                      \
        for (int i = 0; i < 8; ++i) a2[i] = packdup(As[kk][ty * 8 + i]);       \
        _Pragma("unroll")                                                      \
        for (int j = 0; j < 4; ++j)                                            \
            b2[j] = *(const u64*)&Bs[kk][tx * 8 + 2 * j];                      \
        _Pragma("unroll")                                                      \
        for (int i = 0; i < 8; ++i)                                            \
            _Pragma("unroll")                                                  \
            for (int j = 0; j < 4; ++j)                                        \
                fma2(acc2[i][j], a2[i], b2[j]);                                \
    }                                                                          \
    __syncthreads();

// extract scalar acc (i, j) — j in 0..7
#define ACCV(i, j) (((j) & 1) ? unpk(acc2[(i)][(j) >> 1]).y                    \
                              : unpk(acc2[(i)][(j) >> 1]).x)

#define ACC_INIT()                                                             \
    u64 acc2[8][4];                                                            \
    _Pragma("unroll")                                                          \
    for (int i = 0; i < 8; ++i)                                                \
        _Pragma("unroll")                                                      \
        for (int j = 0; j < 4; ++j) acc2[i][j] = 0ull;

// ---------------------------------------------------------------------------
// Kernel 1: conv1 1x1 s1.  C[co=128][j=100352] = W1[128,256] * X[256, j]
// ---------------------------------------------------------------------------
__global__ __launch_bounds__(256, 2)
void conv1_k(const float* __restrict__ x, const float* __restrict__ w,
             const float* __restrict__ gg, const float* __restrict__ bb,
             const float* __restrict__ mm, const float* __restrict__ vv,
             const float* __restrict__ ss)
{
    __shared__ float As[16][128];
    __shared__ float Bs[16][128];
    const int t  = threadIdx.x;
    const int tx = t & 15, ty = t >> 4;
    const int jcol = t & 127, krow = t >> 7;
    const int jg = blockIdx.x * 128 + jcol;
    const int n  = jg / 3136, p = jg - n * 3136;
    const float* xb = x + n * 802816 + p;
    const int ai = t >> 1;
    const int ak = (t & 1) * 8;

    ACC_INIT();

    for (int k0 = 0; k0 < 256; k0 += 16) {
        const float* wp = w + ai * 256 + k0 + ak;
#pragma unroll
        for (int r = 0; r < 8; ++r) As[ak + r][ai] = wp[r];
        const float* xp = xb + (k0 + krow * 8) * 3136;
#pragma unroll
        for (int r = 0; r < 8; ++r) Bs[krow * 8 + r][jcol] = xp[r * 3136];
        GEMM_COMPUTE_STEP();
    }

    const float s = *ss;
    float inv_[8], bia_[8];
#pragma unroll
    for (int i = 0; i < 8; ++i) {
        int co = ty * 8 + i;
        float iv = gg[co] / sqrtf(vv[co] + EPSBN);
        inv_[i] = iv;
        bia_[i] = bb[co] - mm[co] * iv;
    }
#pragma unroll
    for (int j = 0; j < 8; ++j) {
        int jj = blockIdx.x * 128 + tx * 8 + j;
        int nn = jj / 3136, pp = jj - nn * 3136;
        float* op = g_buf1 + nn * 401408 + pp;
#pragma unroll
        for (int i = 0; i < 8; ++i) {
            float y = ACCV(i, j) * inv_[i] + bia_[i];
            op[(ty * 8 + i) * 3136] = fmaxf(fq(y, s), 0.f);
        }
    }
}

// ---------------------------------------------------------------------------
// Kernel 2: conv2 3x3 s2 pad1, 128->128. 9 accumulated 1x1-GEMM taps.
// ---------------------------------------------------------------------------
__global__ __launch_bounds__(256, 2)
void conv2_k(const float* __restrict__ w,
             const float* __restrict__ gg, const float* __restrict__ bb,
             const float* __restrict__ mm, const float* __restrict__ vv,
             const float* __restrict__ ss)
{
    __shared__ float As[16][128];
    __shared__ float Bs[16][128];
    const int t  = threadIdx.x;
    const int tx = t & 15, ty = t >> 4;
    const int jcol = t & 127, krow = t >> 7;
    const int jg = blockIdx.x * 128 + jcol;
    const int n  = jg / 784, p = jg - n * 784;
    const int ho = p / 28, wo = p - ho * 28;
    const int h0 = 2 * ho - 1, w0 = 2 * wo - 1;
    const float* o1n = g_buf1 + n * 401408;
    const int ai = t >> 1;
    const int ak = (t & 1) * 8;

    ACC_INIT();

    for (int tap = 0; tap < 9; ++tap) {
        const int kh = tap / 3, kw = tap - kh * 3;
        const int h = h0 + kh, wd = w0 + kw;
        const bool valid = ((unsigned)h < 56u) && ((unsigned)wd < 56u);
        const int off = h * 56 + wd;
        for (int k0 = 0; k0 < 128; k0 += 16) {
#pragma unroll
            for (int r = 0; r < 8; ++r)
                As[ak + r][ai] = w[(ai * 128 + k0 + ak + r) * 9 + tap];
#pragma unroll
            for (int r = 0; r < 8; ++r) {
                int k = k0 + krow * 8 + r;
                Bs[krow * 8 + r][jcol] = valid ? o1n[k * 3136 + off] : 0.f;
            }
            GEMM_COMPUTE_STEP();
        }
    }

    const float s = *ss;
    float inv_[8], bia_[8];
#pragma unroll
    for (int i = 0; i < 8; ++i) {
        int co = ty * 8 + i;
        float iv = gg[co] / sqrtf(vv[co] + EPSBN);
        inv_[i] = iv;
        bia_[i] = bb[co] - mm[co] * iv;
    }
#pragma unroll
    for (int j = 0; j < 8; ++j) {
        int jj = blockIdx.x * 128 + tx * 8 + j;
        int nn = jj / 784, pp = jj - nn * 784;
        float* op = g_buf2 + nn * 100352 + pp;
#pragma unroll
        for (int i = 0; i < 8; ++i) {
            float y = ACCV(i, j) * inv_[i] + bia_[i];
            op[(ty * 8 + i) * 784] = fmaxf(fq(y, s), 0.f);
        }
    }
}

// ---------------------------------------------------------------------------
// Kernel 3: conv3 1x1, 128->512, no relu. Writes fq values into g_buf1.
// ---------------------------------------------------------------------------
__global__ __launch_bounds__(256, 2)
void conv3_k(const float* __restrict__ w,
             const float* __restrict__ gg, const float* __restrict__ bb,
             const float* __restrict__ mm, const float* __restrict__ vv,
             const float* __restrict__ ss)
{
    __shared__ float As[16][128];
    __shared__ float Bs[16][128];
    const int t  = threadIdx.x;
    const int tx = t & 15, ty = t >> 4;
    const int jcol = t & 127, krow = t >> 7;
    const int coT = blockIdx.y * 128;
    const int jg = blockIdx.x * 128 + jcol;
    const int n  = jg / 784, p = jg - n * 784;
    const float* o2b = g_buf2 + n * 100352 + p;
    const int ai = t >> 1;
    const int ak = (t & 1) * 8;

    ACC_INIT();

    for (int k0 = 0; k0 < 128; k0 += 16) {
        const float* wp = w + (coT + ai) * 128 + k0 + ak;
#pragma unroll
        for (int r = 0; r < 8; ++r) As[ak + r][ai] = wp[r];
        const float* xp = o2b + (k0 + krow * 8) * 784;
#pragma unroll
        for (int r = 0; r < 8; ++r) Bs[krow * 8 + r][jcol] = xp[r * 784];
        GEMM_COMPUTE_STEP();
    }

    const float s = *ss;
    float inv_[8], bia_[8];
#pragma unroll
    for (int i = 0; i < 8; ++i) {
        int co = coT + ty * 8 + i;
        float iv = gg[co] / sqrtf(vv[co] + EPSBN);
        inv_[i] = iv;
        bia_[i] = bb[co] - mm[co] * iv;
    }
#pragma unroll
    for (int j = 0; j < 8; ++j) {
        int jj = blockIdx.x * 128 + tx * 8 + j;
        int nn = jj / 784, pp = jj - nn * 784;
        float* op = g_buf1 + nn * 401408 + (coT + ty * 8) * 784 + pp;
#pragma unroll
        for (int i = 0; i < 8; ++i) {
            float y = ACCV(i, j) * inv_[i] + bia_[i];
            op[i * 784] = fq(y, s);
        }
    }
}

// ---------------------------------------------------------------------------
// Kernel 4: shortcut 1x1 s2, 256->512, fq; out = relu(t3 + sc).
// ---------------------------------------------------------------------------
__global__ __launch_bounds__(256, 2)
void conv4_k(const float* __restrict__ x, const float* __restrict__ w,
             const float* __restrict__ gg, const float* __restrict__ bb,
             const float* __restrict__ mm, const float* __restrict__ vv,
             const float* __restrict__ ss, float* __restrict__ out)
{
    __shared__ float As[16][128];
    __shared__ float Bs[16][128];
    const int t  = threadIdx.x;
    const int tx = t & 15, ty = t >> 4;
    const int jcol = t & 127, krow = t >> 7;
    const int coT = blockIdx.y * 128;
    const int jg = blockIdx.x * 128 + jcol;
    const int n  = jg / 784, p = jg - n * 784;
    const int ho = p / 28, wo = p - ho * 28;
    const float* xb = x + n * 802816 + (2 * ho) * 56 + 2 * wo;
    const int ai = t >> 1;
    const int ak = (t & 1) * 8;

    ACC_INIT();

    for (int k0 = 0; k0 < 256; k0 += 16) {
        const float* wp = w + (coT + ai) * 256 + k0 + ak;
#pragma unroll
        for (int r = 0; r < 8; ++r) As[ak + r][ai] = wp[r];
        const float* xp = xb + (k0 + krow * 8) * 3136;
#pragma unroll
        for (int r = 0; r < 8; ++r) Bs[krow * 8 + r][jcol] = xp[r * 3136];
        GEMM_COMPUTE_STEP();
    }

    const float s = *ss;
    float inv_[8], bia_[8];
#pragma unroll
    for (int i = 0; i < 8; ++i) {
        int co = coT + ty * 8 + i;
        float iv = gg[co] / sqrtf(vv[co] + EPSBN);
        inv_[i] = iv;
        bia_[i] = bb[co] - mm[co] * iv;
    }
#pragma unroll
    for (int j = 0; j < 8; ++j) {
        int jj = blockIdx.x * 128 + tx * 8 + j;
        int nn = jj / 784, pp = jj - nn * 784;
        int base = nn * 401408 + (coT + ty * 8) * 784 + pp;
        const float* t3 = g_buf1 + base;
        float* op = out + base;
#pragma unroll
        for (int i = 0; i < 8; ++i) {
            float y  = ACCV(i, j) * inv_[i] + bia_[i];
            float qs = fq(y, s);
            op[i * 784] = fmaxf(t3[i * 784] + qs, 0.f);
        }
    }
}

// ---------------------------------------------------------------------------
extern "C" void kernel_launch(void* const* d_in, const int* in_sizes, int n_in,
                              void* d_out, int out_size)
{
    const float* x  = (const float*)d_in[0];
    const float* w1 = (const float*)d_in[1];
    const float* g1 = (const float*)d_in[2];
    const float* b1 = (const float*)d_in[3];
    const float* m1 = (const float*)d_in[4];
    const float* v1 = (const float*)d_in[5];
    const float* s1 = (const float*)d_in[6];
    const float* w2 = (const float*)d_in[7];
    const float* g2 = (const float*)d_in[8];
    const float* b2 = (const float*)d_in[9];
    const float* m2 = (const float*)d_in[10];
    const float* v2 = (const float*)d_in[11];
    const float* s2 = (const float*)d_in[12];
    const float* w3 = (const float*)d_in[13];
    const float* g3 = (const float*)d_in[14];
    const float* b3 = (const float*)d_in[15];
    const float* m3 = (const float*)d_in[16];
    const float* v3 = (const float*)d_in[17];
    const float* s3 = (const float*)d_in[18];
    const float* ws = (const float*)d_in[19];
    const float* gs = (const float*)d_in[20];
    const float* bs = (const float*)d_in[21];
    const float* ms = (const float*)d_in[22];
    const float* vs = (const float*)d_in[23];
    const float* ss = (const float*)d_in[24];

    conv1_k<<<784, 256>>>(x, w1, g1, b1, m1, v1, s1);
    conv2_k<<<196, 256>>>(w2, g2, b2, m2, v2, s2);
    conv3_k<<<dim3(196, 4), 256>>>(w3, g3, b3, m3, v3, s3);
    conv4_k<<<dim3(196, 4), 256>>>(x, ws, gs, bs, ms, vs, ss, (float*)d_out);
}